// round 10
// baseline (speedup 1.0000x reference)
#include <cuda_runtime.h>
#include <cstdint>

// out[n,h,d] = sum_j x[n,j,d] * FM[j+1,h] * Agg[0,j,h]
// (the reference's sort/gap/code machinery telescopes to this linear map)
//
// R9: floor-converged form. ~700 GB/s is a chip-level ceiling (DVFS-state
// HBM) invariant to 7 structurally different kernels; read-time 4.2MB/700GB/s
// = 6.0us matches every measurement. This round removes the last structural
// slack: single wave (grid=128, 1 block/n), 16 warps/SM (block=512),
// all-lane stores (lane jg stores h=jg), 4-way j-split + 2 shfl rounds.

#define S_DIM 16
#define H_DIM 4
#define N_DIM 128
#define D_DIM 512

__global__ void __launch_bounds__(512) cie_linear_kernel(
    const float* __restrict__ x,     // (N, S, D)
    const float* __restrict__ FM,    // (S+1, H)
    const float* __restrict__ Agg,   // (1, S, H)
    float* __restrict__ out)         // (N, H, D)
{
    __shared__ float W[S_DIM][H_DIM];
    const int tid = threadIdx.x;
    if (tid < S_DIM * H_DIM) {
        int j = tid / H_DIM, h = tid % H_DIM;
        W[j][h] = FM[(j + 1) * H_DIM + h] * Agg[j * H_DIM + h];
    }
    __syncthreads();

    const int n   = blockIdx.x;        // one block per n, single wave
    const int col = tid >> 2;          // 0..127 -> d4 column
    const int jg  = tid & 3;           // j-group: j = jg*4 .. jg*4+3

    const float4* xp = reinterpret_cast<const float4*>(
        x + (size_t)n * S_DIM * D_DIM) + col;

    // 4 batched float4 loads; for each j, 8 lanes cover 128B contiguous.
    float4 v0 = __ldg(xp + (jg * 4 + 0) * (D_DIM / 4));
    float4 v1 = __ldg(xp + (jg * 4 + 1) * (D_DIM / 4));
    float4 v2 = __ldg(xp + (jg * 4 + 2) * (D_DIM / 4));
    float4 v3 = __ldg(xp + (jg * 4 + 3) * (D_DIM / 4));

    float4 acc[H_DIM];
#pragma unroll
    for (int h = 0; h < H_DIM; h++) {
        const float w0 = W[jg * 4 + 0][h];
        const float w1 = W[jg * 4 + 1][h];
        const float w2 = W[jg * 4 + 2][h];
        const float w3 = W[jg * 4 + 3][h];
        float ax, ay, az, aw;
        ax = v0.x * w0; ay = v0.y * w0; az = v0.z * w0; aw = v0.w * w0;
        ax = fmaf(v1.x, w1, ax); ay = fmaf(v1.y, w1, ay);
        az = fmaf(v1.z, w1, az); aw = fmaf(v1.w, w1, aw);
        ax = fmaf(v2.x, w2, ax); ay = fmaf(v2.y, w2, ay);
        az = fmaf(v2.z, w2, az); aw = fmaf(v2.w, w2, aw);
        ax = fmaf(v3.x, w3, ax); ay = fmaf(v3.y, w3, ay);
        az = fmaf(v3.z, w3, az); aw = fmaf(v3.w, w3, aw);
        acc[h] = make_float4(ax, ay, az, aw);
    }

    // Fold the 4 j-groups across adjacent lanes (xor 1, then 2).
#pragma unroll
    for (int m = 1; m <= 2; m <<= 1) {
#pragma unroll
        for (int h = 0; h < H_DIM; h++) {
            acc[h].x += __shfl_xor_sync(0xffffffffu, acc[h].x, m);
            acc[h].y += __shfl_xor_sync(0xffffffffu, acc[h].y, m);
            acc[h].z += __shfl_xor_sync(0xffffffffu, acc[h].z, m);
            acc[h].w += __shfl_xor_sync(0xffffffffu, acc[h].w, m);
        }
    }

    // After the fold, all 4 lanes of a d4 group hold the full sums.
    // Lane jg stores head h=jg: one STG.128 per thread, no idle lanes.
    float4* op = reinterpret_cast<float4*>(
        out + (size_t)n * H_DIM * D_DIM) + col;
    op[jg * (D_DIM / 4)] = acc[jg];
}

extern "C" void kernel_launch(void* const* d_in, const int* in_sizes, int n_in,
                              void* d_out, int out_size) {
    const float* x   = (const float*)d_in[0];   // (128,16,512) f32
    const float* FM  = (const float*)d_in[1];   // (17,4) f32
    const float* Agg = (const float*)d_in[2];   // (1,16,4) f32
    // d_in[3] = source_index, unused: the table gather telescopes away.
    float* out = (float*)d_out;                 // (128,4,512) f32

    cie_linear_kernel<<<N_DIM, 512>>>(x, FM, Agg, out);
}